// round 15
// baseline (speedup 1.0000x reference)
#include <cuda_runtime.h>
#include <cuda_fp16.h>
#include <math.h>
#include <stdint.h>

#define T     4096
#define H     16
#define HKV   4
#define D     128
#define HID   2048
#define QKV_N ((H + 2 * HKV) * D)   // 3072
#define QD    (H * D)               // 2048
#define KD    (HKV * D)             // 512
#define EPSV  1e-5f
#define GK    2048
#define GCH   64
#define NCH   (GK / GCH)            // 32 chunks

// fp16 scratch
__device__ __half g_qkvh[T * QKV_N];   // QKV projection output (fp16)
__device__ __half g_hsf[T * HID];
__device__ __half g_wqf[QKV_N * HID];
__device__ __half g_wof[HID * QD];
__device__ __half g_qf[T * QD];
__device__ __half g_kf[T * KD];
__device__ __half g_atf[T * QD];

// ---------------------------------------------------------------------------
// helpers (sm_80-level PTX only)
// ---------------------------------------------------------------------------
__device__ __forceinline__ uint32_t smem_u32(const void* p) {
    uint32_t a;
    asm("{ .reg .u64 t; cvta.to.shared.u64 t, %1; cvt.u32.u64 %0, t; }"
        : "=r"(a) : "l"(p));
    return a;
}
__device__ __forceinline__ void cp16(uint32_t dst, const void* src) {
    asm volatile("cp.async.cg.shared.global [%0], [%1], 16;"
                 :: "r"(dst), "l"(src));
}
__device__ __forceinline__ void ldsm4(uint32_t* r, uint32_t addr) {
    asm volatile("ldmatrix.sync.aligned.m8n8.x4.shared.b16 {%0,%1,%2,%3}, [%4];"
                 : "=r"(r[0]), "=r"(r[1]), "=r"(r[2]), "=r"(r[3]) : "r"(addr));
}
__device__ __forceinline__ void ldsm4t(uint32_t* r, uint32_t addr) {
    asm volatile("ldmatrix.sync.aligned.m8n8.x4.trans.shared.b16 {%0,%1,%2,%3}, [%4];"
                 : "=r"(r[0]), "=r"(r[1]), "=r"(r[2]), "=r"(r[3]) : "r"(addr));
}
__device__ __forceinline__ void ldsm2(uint32_t* r, uint32_t addr) {
    asm volatile("ldmatrix.sync.aligned.m8n8.x2.shared.b16 {%0,%1}, [%2];"
                 : "=r"(r[0]), "=r"(r[1]) : "r"(addr));
}
__device__ __forceinline__ void mma16816(float* c, const uint32_t* a,
                                         const uint32_t* b) {
    asm volatile(
        "mma.sync.aligned.m16n8k16.row.col.f32.f16.f16.f32 "
        "{%0,%1,%2,%3}, {%4,%5,%6,%7}, {%8,%9}, {%0,%1,%2,%3};"
        : "+f"(c[0]), "+f"(c[1]), "+f"(c[2]), "+f"(c[3])
        : "r"(a[0]), "r"(a[1]), "r"(a[2]), "r"(a[3]), "r"(b[0]), "r"(b[1]));
}
__device__ __forceinline__ uint32_t packh2(float a, float b) {
    __half2 h = __floats2half2_rn(a, b);
    return *(uint32_t*)&h;
}
// single-MUFU exp2
__device__ __forceinline__ float ex2(float x) {
    float y;
    asm("ex2.approx.f32 %0, %1;" : "=f"(y) : "f"(x));
    return y;
}
// exp2 on the fma/alu pipes (no MUFU): round-to-nearest magic + cubic minimax
// on f in [-0.5,0.5]; rel err ~1e-5. Clamp keeps masked -1e30 inputs safe (->0).
__device__ __forceinline__ float ex2_poly(float x) {
    x = fmaxf(x, -126.0f);
    float z  = x + 12582912.0f;            // 1.5*2^23 magic (round-to-nearest)
    int   zi = __float_as_int(z);
    float fi = z - 12582912.0f;            // rint(x)
    float f  = x - fi;                     // f in [-0.5, 0.5]
    float p  = 0.05558263f;
    p = fmaf(p, f, 0.24015361f);
    p = fmaf(p, f, 0.69315308f);
    p = fmaf(p, f, 0.99999994f);
    return __int_as_float(__float_as_int(p) + ((zi - 0x4B400000) << 23));
}
// 256B rows, 16B-granular XOR swizzle (flash buffers)
__device__ __forceinline__ uint32_t swz(uint32_t base, int row, int col16) {
    return base + row * 256 + ((col16 ^ (row & 7)) << 4);
}

// ---------------------------------------------------------------------------
// fused fp32 -> fp16 conversion (vectorized, 1 launch)
// ---------------------------------------------------------------------------
#define N_HS  (T * HID)
#define N_WQ  (QKV_N * HID)
#define N_WO  (HID * QD)

__global__ __launch_bounds__(256) void cvt_f16(const float* __restrict__ hs,
                                               const float* __restrict__ wq,
                                               const float* __restrict__ wo) {
    long idx = ((long)blockIdx.x * 256 + threadIdx.x) * 4;
    const float* src;
    __half* dst;
    long off;
    if (idx < N_HS)             { src = hs; dst = g_hsf; off = idx; }
    else if (idx < N_HS + N_WQ) { src = wq; dst = g_wqf; off = idx - N_HS; }
    else                        { src = wo; dst = g_wof; off = idx - N_HS - N_WQ; }
    float4 v = *(const float4*)(src + off);
    uint2 w = make_uint2(packh2(v.x, v.y), packh2(v.z, v.w));
    *(uint2*)(dst + off) = w;
}

// ---------------------------------------------------------------------------
// mma.sync fp16 NT GEMM, BK=64, single barrier per chunk, 3-stage, 2 CTAs/SM.
// ---------------------------------------------------------------------------
#define TILE_B   (128 * 144)
#define STAGE_B  (2 * TILE_B)
#define GSMEM    (3 * STAGE_B)

template<bool HALF_OUT>
__global__ __launch_bounds__(256, 2)
void gemm_hmma(const __half* __restrict__ A,
               const __half* __restrict__ B,
               void* __restrict__ Cv, int N) {
    extern __shared__ char smem[];
    const uint32_t sbase = smem_u32(smem);
    const int tid  = threadIdx.x;
    const int wid  = tid >> 5;
    const int lane = tid & 31;
    const int wm   = wid & 1;
    const int wn   = wid >> 1;
    const int bm   = blockIdx.y * 128;
    const int bn   = blockIdx.x * 128;

    const __half* srcs[2] = {A + (size_t)bm * GK, B + (size_t)bn * GK};

    auto load_chunk = [&](int stage, int k0) {
        uint32_t db = sbase + stage * STAGE_B;
#pragma unroll
        for (int t = 0; t < 2; t++) {
            const __half* s = srcs[t] + k0;
#pragma unroll
            for (int i = 0; i < 4; i++) {
                int seg = i * 256 + tid;
                int row = seg >> 3, c16 = seg & 7;
                cp16(db + t * TILE_B + row * 144 + c16 * 16,
                     s + (size_t)row * GK + c16 * 8);
            }
        }
        asm volatile("cp.async.commit_group;" ::: "memory");
    };

    float acc[4][4][4];
#pragma unroll
    for (int mt = 0; mt < 4; mt++)
#pragma unroll
        for (int nt = 0; nt < 4; nt++)
#pragma unroll
            for (int r = 0; r < 4; r++) acc[mt][nt][r] = 0.0f;

    load_chunk(0, 0);
    load_chunk(1, GCH);

    const int arow  = lane & 15;
    const int akoff = (lane >> 4) * 16;
    const int brow  = lane & 7;
    const int bkoff = ((lane >> 3) & 1) * 16;

    for (int i = 0; i < NCH; i++) {
        if (i + 1 < NCH)
            asm volatile("cp.async.wait_group 1;" ::: "memory");
        else
            asm volatile("cp.async.wait_group 0;" ::: "memory");
        __syncthreads();
        if (i + 2 < NCH) load_chunk((i + 2) % 3, (i + 2) * GCH);

        uint32_t s0 = sbase + (i % 3) * STAGE_B;
        uint32_t aB = s0, bB = s0 + TILE_B;

#pragma unroll
        for (int kk = 0; kk < 4; kk++) {
            const int kb = kk * 32;
            uint32_t af[4][4], bf[4][2];
#pragma unroll
            for (int mt = 0; mt < 4; mt++)
                ldsm4(af[mt], aB + (uint32_t)((wm * 64 + mt * 16 + arow) * 144 + kb + akoff));
#pragma unroll
            for (int nt = 0; nt < 4; nt++)
                ldsm2(bf[nt], bB + (uint32_t)((wn * 32 + nt * 8 + brow) * 144 + kb + bkoff));
#pragma unroll
            for (int mt = 0; mt < 4; mt++)
#pragma unroll
                for (int nt = 0; nt < 4; nt++)
                    mma16816(acc[mt][nt], af[mt], bf[nt]);
        }
    }

#pragma unroll
    for (int mt = 0; mt < 4; mt++) {
        const int row0 = bm + wm * 64 + mt * 16 + (lane >> 2);
#pragma unroll
        for (int nt = 0; nt < 4; nt++) {
            const int col = bn + wn * 32 + nt * 8 + (lane & 3) * 2;
            if (HALF_OUT) {
                __half* C = (__half*)Cv;
                *(uint32_t*)&C[(size_t)row0 * N + col] =
                    packh2(acc[mt][nt][0], acc[mt][nt][1]);
                *(uint32_t*)&C[(size_t)(row0 + 8) * N + col] =
                    packh2(acc[mt][nt][2], acc[mt][nt][3]);
            } else {
                float* C = (float*)Cv;
                *(float2*)&C[(size_t)row0 * N + col] =
                    make_float2(acc[mt][nt][0], acc[mt][nt][1]);
                *(float2*)&C[(size_t)(row0 + 8) * N + col] =
                    make_float2(acc[mt][nt][2], acc[mt][nt][3]);
            }
        }
    }
}

// ---------------------------------------------------------------------------
// RoPE + RMSNorm, reads fp16 qkv. Emits fp16 q (pre-scaled), k.
// ---------------------------------------------------------------------------
__global__ __launch_bounds__(256) void rope_norm_kernel(
    const int* __restrict__ positions,
    const float* __restrict__ qnw,
    const float* __restrict__ knw) {
    const int t    = blockIdx.x;
    const int tid  = threadIdx.x;
    const int lane = tid & 31;
    const float pos  = (float)positions[t];
    const float qpre = 0.08838834764831845f * 1.4426950408889634f;

    __shared__ float cs[64], sn[64];
    __shared__ float red[8];

    if (tid < 64) {
        float inv = powf(10000.0f, -(float)(2 * tid) * (1.0f / 128.0f));
        sincosf(pos * inv, &sn[tid], &cs[tid]);
    }
    __syncthreads();

    const __half* base = g_qkvh + (size_t)t * QKV_N;

    const int head = tid >> 4;
    const int c4   = (tid & 15) * 4;
    float av[4], bv[4];
    {
        uint2 ar = *(const uint2*)(base + head * 128 + c4);
        uint2 br = *(const uint2*)(base + head * 128 + 64 + c4);
        __half2* ah = (__half2*)&ar;
        __half2* bh = (__half2*)&br;
        float2 a0 = __half22float2(ah[0]), a1 = __half22float2(ah[1]);
        float2 b0 = __half22float2(bh[0]), b1 = __half22float2(bh[1]);
        av[0] = a0.x; av[1] = a0.y; av[2] = a1.x; av[3] = a1.y;
        bv[0] = b0.x; bv[1] = b0.y; bv[2] = b1.x; bv[3] = b1.y;
    }
    float o1[4], o2[4];
    {
        float ss = 0.0f;
#pragma unroll
        for (int j = 0; j < 4; j++) {
            float cv = cs[c4 + j], sv = sn[c4 + j];
            o1[j] = av[j] * cv - bv[j] * sv;
            o2[j] = bv[j] * cv + av[j] * sv;
            ss += o1[j] * o1[j] + o2[j] * o2[j];
        }
#pragma unroll
        for (int off = 16; off; off >>= 1)
            ss += __shfl_xor_sync(0xffffffffu, ss, off);
        if (lane == 0) red[tid >> 5] = ss;
    }
    __syncthreads();
    {
        float tot = red[0] + red[1] + red[2] + red[3] +
                    red[4] + red[5] + red[6] + red[7];
        float qs = rsqrtf(tot * (1.0f / QD) + EPSV) * qpre;
        float4 w1 = *(const float4*)(qnw + head * 128 + c4);
        float4 w2 = *(const float4*)(qnw + head * 128 + 64 + c4);
        __half* dst = g_qf + (size_t)t * QD + head * 128 + c4;
        *(uint2*)dst = make_uint2(packh2(o1[0] * qs * w1.x, o1[1] * qs * w1.y),
                                  packh2(o1[2] * qs * w1.z, o1[3] * qs * w1.w));
        *(uint2*)(dst + 64) = make_uint2(packh2(o2[0] * qs * w2.x, o2[1] * qs * w2.y),
                                         packh2(o2[2] * qs * w2.z, o2[3] * qs * w2.w));
    }
    __syncthreads();

    const int khead = tid >> 6;
    const int fi    = tid & 63;
    const __half* kp = base + QD + khead * 128 + fi;
    float k1, k2;
    {
        float ka = __half2float(kp[0]), kb = __half2float(kp[64]);
        float cv = cs[fi], sv = sn[fi];
        k1 = ka * cv - kb * sv;
        k2 = kb * cv + ka * sv;
        float ss = k1 * k1 + k2 * k2;
#pragma unroll
        for (int off = 16; off; off >>= 1)
            ss += __shfl_xor_sync(0xffffffffu, ss, off);
        if (lane == 0) red[tid >> 5] = ss;
    }
    __syncthreads();
    {
        float tot = red[0] + red[1] + red[2] + red[3] +
                    red[4] + red[5] + red[6] + red[7];
        float ks = rsqrtf(tot * (1.0f / KD) + EPSV);
        __half* dst = g_kf + (size_t)t * KD + khead * 128 + fi;
        dst[0]  = __float2half_rn(k1 * ks * knw[khead * 128 + fi]);
        dst[64] = __float2half_rn(k2 * ks * knw[khead * 128 + 64 + fi]);
    }
    // V: consumed directly from g_qkvh by flash (no copy)
}

// ---------------------------------------------------------------------------
// flash_mma: causal GQA attention, fp16 mma, software-pipelined.
// CTA: 64 queries x 1 head, 4 warps, 128-key tiles, 2 CTAs/SM.
// Softmax exps split across pipes: half MUFU (ex2.approx), half fma/alu
// (ex2_poly) -- MUFU was co-bottleneck with the tensor pipe at ~1024 cyc
// each per SMSP-tile. K double-buffered, V single-buffered; K(it+2)
// committed after the first barrier, V(it+1) after the post-PV barrier.
// ---------------------------------------------------------------------------
#define QSZ     16384                      // 64 rows x 256 B
#define KSZ     32768                      // 128 rows x 256 B
#define VSZ     32768
#define FSMEM   (QSZ + 2 * KSZ + VSZ)      // 114688 -> 2 CTAs/SM

__global__ __launch_bounds__(128, 2) void flash_mma() {
    extern __shared__ char smem[];
    const uint32_t sbase = smem_u32(smem);
    const int tid  = threadIdx.x;
    const int wg   = tid >> 5;
    const int lane = tid & 31;
    const int h    = blockIdx.y;
    const int kvh  = h >> 2;
    const int qb   = (int)gridDim.x - 1 - (int)blockIdx.x;
    const int q0   = qb * 64;
    const int nt   = qb / 2 + 1;           // 128-key tiles covering [0, q0+64)

    const uint32_t qB = sbase;
    const uint32_t vB = sbase + QSZ + 2 * KSZ;

    auto load_k = [&](int stage, int k0) {
        const __half* ks = g_kf + (size_t)k0 * KD + kvh * D;
        uint32_t kb = sbase + QSZ + stage * KSZ;
#pragma unroll
        for (int i = 0; i < 16; i++) {
            int seg = i * 128 + tid;
            int row = seg >> 4, c = seg & 15;
            cp16(swz(kb, row, c), ks + (size_t)row * KD + c * 8);
        }
    };
    auto load_v = [&](int k0) {
        const __half* vs = g_qkvh + (size_t)k0 * QKV_N + QD + KD + kvh * D;
#pragma unroll
        for (int i = 0; i < 16; i++) {
            int seg = i * 128 + tid;
            int row = seg >> 4, c = seg & 15;
            cp16(swz(vB, row, c), vs + (size_t)row * QKV_N + c * 8);
        }
    };

    // ---- prologue: {Q, K0, V0} then {K1} ----
    {
        const __half* qs = g_qf + (size_t)q0 * QD + h * D;
#pragma unroll
        for (int i = 0; i < 8; i++) {
            int seg = i * 128 + tid;
            int row = seg >> 4, c = seg & 15;
            cp16(swz(qB, row, c), qs + (size_t)row * QD + c * 8);
        }
        load_k(0, 0);
        load_v(0);
        asm volatile("cp.async.commit_group;" ::: "memory");
    }
    if (nt > 1) {
        load_k(1, 128);
        asm volatile("cp.async.commit_group;" ::: "memory");
        asm volatile("cp.async.wait_group 1;" ::: "memory");
    } else {
        asm volatile("cp.async.wait_group 0;" ::: "memory");
    }
    __syncthreads();

    // per-lane fragment coordinates
    const int qrow = wg * 16 + (lane & 15);
    const int qhi  = lane >> 4;
    const int krow = ((lane >> 4) << 3) + (lane & 7);
    const int khi  = (lane >> 3) & 1;
    const int vrow = (((lane >> 3) & 1) << 3) + (lane & 7);
    const int vhi  = lane >> 4;
    const int r_lo = q0 + wg * 16 + (lane >> 2);
    const int r_hi = r_lo + 8;

    float o[16][4];
#pragma unroll
    for (int ntl = 0; ntl < 16; ntl++)
#pragma unroll
        for (int r = 0; r < 4; r++) o[ntl][r] = 0.0f;
    float m_lo = -1e30f, m_hi = -1e30f, l_lo = 0.0f, l_hi = 0.0f;

    float s[16][4];

    auto compute_S = [&](int stage) {
        const uint32_t kb = sbase + QSZ + stage * KSZ;
#pragma unroll
        for (int ntl = 0; ntl < 16; ntl++)
#pragma unroll
            for (int r = 0; r < 4; r++) s[ntl][r] = 0.0f;
#pragma unroll
        for (int kk = 0; kk < 8; kk++) {
            uint32_t af[4];
            ldsm4(af, swz(qB, qrow, kk * 2 + qhi));
#pragma unroll
            for (int np = 0; np < 8; np++) {
                uint32_t bf[4];
                ldsm4(bf, swz(kb, np * 16 + krow, kk * 2 + khi));
                mma16816(s[2 * np],     af, &bf[0]);
                mma16816(s[2 * np + 1], af, &bf[2]);
            }
        }
    };

    compute_S(0);

    for (int it = 0; it < nt; it++) {
        // ---- softmax(it) ----
        if (it == nt - 1) {
#pragma unroll
            for (int ntl = 0; ntl < 16; ntl++) {
#pragma unroll
                for (int c = 0; c < 2; c++) {
                    int key = it * 128 + ntl * 8 + (lane & 3) * 2 + c;
                    if (key > r_lo) s[ntl][c]     = -1e30f;
                    if (key > r_hi) s[ntl][2 + c] = -1e30f;
                }
            }
        }
        float mx_lo = -1e30f, mx_hi = -1e30f;
#pragma unroll
        for (int ntl = 0; ntl < 16; ntl++) {
            mx_lo = fmaxf(mx_lo, fmaxf(s[ntl][0], s[ntl][1]));
            mx_hi = fmaxf(mx_hi, fmaxf(s[ntl][2], s[ntl][3]));
        }
        mx_lo = fmaxf(mx_lo, __shfl_xor_sync(0xffffffffu, mx_lo, 1));
        mx_lo = fmaxf(mx_lo, __shfl_xor_sync(0xffffffffu, mx_lo, 2));
        mx_hi = fmaxf(mx_hi, __shfl_xor_sync(0xffffffffu, mx_hi, 1));
        mx_hi = fmaxf(mx_hi, __shfl_xor_sync(0xffffffffu, mx_hi, 2));
        float mn_lo = fmaxf(m_lo, mx_lo);
        float mn_hi = fmaxf(m_hi, mx_hi);
        float cr_lo = ex2(m_lo - mn_lo);
        float cr_hi = ex2(m_hi - mn_hi);
        m_lo = mn_lo; m_hi = mn_hi;

        uint32_t p2[16][2];
        float sum_lo = 0.0f, sum_hi = 0.0f;
#pragma unroll
        for (int ntl = 0; ntl < 16; ntl++) {
            // hybrid: lo-rows on MUFU, hi-rows on the fma/alu poly path
            float p0 = ex2(s[ntl][0] - m_lo);
            float p1 = ex2(s[ntl][1] - m_lo);
            float pc = ex2_poly(s[ntl][2] - m_hi);
            float p3 = ex2_poly(s[ntl][3] - m_hi);
            sum_lo += p0 + p1;
            sum_hi += pc + p3;
            p2[ntl][0] = packh2(p0, p1);
            p2[ntl][1] = packh2(pc, p3);
        }
        bool need = (cr_lo != 1.0f) || (cr_hi != 1.0f);
        if (__any_sync(0xffffffffu, need)) {
            l_lo = l_lo * cr_lo + sum_lo;
            l_hi = l_hi * cr_hi + sum_hi;
#pragma unroll
            for (int ntl = 0; ntl < 16; ntl++) {
                o[ntl][0] *= cr_lo; o[ntl][1] *= cr_lo;
                o[ntl][2] *= cr_hi; o[ntl][3] *= cr_hi;
            }
        } else {
            l_lo += sum_lo;
            l_hi += sum_hi;
        }

        // ---- V(it) resident ----
        asm volatile("cp.async.wait_group 0;" ::: "memory");
        __syncthreads();

        // ---- K(it+2) commit: stage it&1 free ----
        if (it + 2 < nt) {
            load_k(it & 1, (it + 2) * 128);
            asm volatile("cp.async.commit_group;" ::: "memory");
        }

        // ---- PV(it) ----
#pragma unroll
        for (int kk = 0; kk < 8; kk++) {
            uint32_t pa[4] = {p2[2 * kk][0], p2[2 * kk][1],
                              p2[2 * kk + 1][0], p2[2 * kk + 1][1]};
#pragma unroll
            for (int nd = 0; nd < 8; nd++) {
                uint32_t vf[4];
                ldsm4t(vf, swz(vB, kk * 16 + vrow, nd * 2 + vhi));
                mma16816(o[2 * nd],     pa, &vf[0]);
                mma16816(o[2 * nd + 1], pa, &vf[2]);
            }
        }
        __syncthreads();                      // V buffer free

        // ---- V(it+1) commit, then S(it+1) ----
        if (it + 1 < nt) {
            load_v((it + 1) * 128);
            asm volatile("cp.async.commit_group;" ::: "memory");
            compute_S((it + 1) & 1);
        }
    }

    // ---- epilogue ----
    l_lo += __shfl_xor_sync(0xffffffffu, l_lo, 1);
    l_lo += __shfl_xor_sync(0xffffffffu, l_lo, 2);
    l_hi += __shfl_xor_sync(0xffffffffu, l_hi, 1);
    l_hi += __shfl_xor_sync(0xffffffffu, l_hi, 2);
    const float inv_lo = 1.0f / l_lo;
    const float inv_hi = 1.0f / l_hi;
#pragma unroll
    for (int ntl = 0; ntl < 16; ntl++) {
        int col = h * D + ntl * 8 + (lane & 3) * 2;
        *(uint32_t*)&g_atf[(size_t)r_lo * QD + col] =
            packh2(o[ntl][0] * inv_lo, o[ntl][1] * inv_lo);
        *(uint32_t*)&g_atf[(size_t)r_hi * QD + col] =
            packh2(o[ntl][2] * inv_hi, o[ntl][3] * inv_hi);
    }
}

// ---------------------------------------------------------------------------
// Launch
// ---------------------------------------------------------------------------
extern "C" void kernel_launch(void* const* d_in, const int* in_sizes, int n_in,
                              void* d_out, int out_size) {
    const int*   positions = (const int*)d_in[0];
    const float* hs        = (const float*)d_in[1];
    const float* w_qkv     = (const float*)d_in[2];
    const float* w_o       = (const float*)d_in[3];
    const float* qnw       = (const float*)d_in[4];
    const float* knw       = (const float*)d_in[5];
    float*       out       = (float*)d_out;

    __half *qkvh, *hsf, *wqf, *wof, *atf;
    cudaGetSymbolAddress((void**)&qkvh, g_qkvh);
    cudaGetSymbolAddress((void**)&hsf, g_hsf);
    cudaGetSymbolAddress((void**)&wqf, g_wqf);
    cudaGetSymbolAddress((void**)&wof, g_wof);
    cudaGetSymbolAddress((void**)&atf, g_atf);

    static bool attr_set = false;
    if (!attr_set) {
        cudaFuncSetAttribute(gemm_hmma<true>,
                             cudaFuncAttributeMaxDynamicSharedMemorySize, GSMEM);
        cudaFuncSetAttribute(gemm_hmma<false>,
                             cudaFuncAttributeMaxDynamicSharedMemorySize, GSMEM);
        cudaFuncSetAttribute(flash_mma,
                             cudaFuncAttributeMaxDynamicSharedMemorySize, FSMEM);
        attr_set = true;
    }

    // 1) fused fp32->fp16 conversions
    cvt_f16<<<(N_HS + N_WQ + N_WO) / 1024, 256>>>(hs, w_qkv, w_o);
    // 2) QKV projection (fp16 output)
    {
        dim3 grid(QKV_N / 128, T / 128);
        gemm_hmma<true><<<grid, 256, GSMEM>>>(hsf, wqf, qkvh, QKV_N);
    }
    // 3) RoPE + RMSNorm (reads fp16 qkv)
    rope_norm_kernel<<<T, 256>>>(positions, qnw, knw);
    // 4) Causal GQA attention (hybrid MUFU/poly softmax)
    {
        dim3 grid(T / 64, H);
        flash_mma<<<grid, 128, FSMEM>>>();
    }
    // 5) Output projection (fp32 output)
    {
        dim3 grid(HID / 128, T / 128);
        gemm_hmma<false><<<grid, 256, GSMEM>>>(atf, wof, out, HID);
    }
}

// round 16
// speedup vs baseline: 1.0523x; 1.0523x over previous
#include <cuda_runtime.h>
#include <cuda_fp16.h>
#include <math.h>
#include <stdint.h>

#define T     4096
#define H     16
#define HKV   4
#define D     128
#define HID   2048
#define QKV_N ((H + 2 * HKV) * D)   // 3072
#define QD    (H * D)               // 2048
#define KD    (HKV * D)             // 512
#define EPSV  1e-5f
#define GK    2048
#define GCH   64
#define NCH   (GK / GCH)            // 32 chunks

// fp16 scratch
__device__ __half g_qkvh[T * QKV_N];   // QKV projection output (fp16)
__device__ __half g_hsf[T * HID];
__device__ __half g_wqf[QKV_N * HID];
__device__ __half g_wof[HID * QD];
__device__ __half g_qf[T * QD];
__device__ __half g_kf[T * KD];
__device__ __half g_atf[T * QD];

// ---------------------------------------------------------------------------
// helpers (sm_80-level PTX only)
// ---------------------------------------------------------------------------
__device__ __forceinline__ uint32_t smem_u32(const void* p) {
    uint32_t a;
    asm("{ .reg .u64 t; cvta.to.shared.u64 t, %1; cvt.u32.u64 %0, t; }"
        : "=r"(a) : "l"(p));
    return a;
}
__device__ __forceinline__ void cp16(uint32_t dst, const void* src) {
    asm volatile("cp.async.cg.shared.global [%0], [%1], 16;"
                 :: "r"(dst), "l"(src));
}
__device__ __forceinline__ void ldsm4(uint32_t* r, uint32_t addr) {
    asm volatile("ldmatrix.sync.aligned.m8n8.x4.shared.b16 {%0,%1,%2,%3}, [%4];"
                 : "=r"(r[0]), "=r"(r[1]), "=r"(r[2]), "=r"(r[3]) : "r"(addr));
}
__device__ __forceinline__ void ldsm4t(uint32_t* r, uint32_t addr) {
    asm volatile("ldmatrix.sync.aligned.m8n8.x4.trans.shared.b16 {%0,%1,%2,%3}, [%4];"
                 : "=r"(r[0]), "=r"(r[1]), "=r"(r[2]), "=r"(r[3]) : "r"(addr));
}
__device__ __forceinline__ void mma16816(float* c, const uint32_t* a,
                                         const uint32_t* b) {
    asm volatile(
        "mma.sync.aligned.m16n8k16.row.col.f32.f16.f16.f32 "
        "{%0,%1,%2,%3}, {%4,%5,%6,%7}, {%8,%9}, {%0,%1,%2,%3};"
        : "+f"(c[0]), "+f"(c[1]), "+f"(c[2]), "+f"(c[3])
        : "r"(a[0]), "r"(a[1]), "r"(a[2]), "r"(a[3]), "r"(b[0]), "r"(b[1]));
}
__device__ __forceinline__ uint32_t packh2(float a, float b) {
    __half2 h = __floats2half2_rn(a, b);
    return *(uint32_t*)&h;
}
// 256B rows, 16B-granular XOR swizzle (flash buffers)
__device__ __forceinline__ uint32_t swz(uint32_t base, int row, int col16) {
    return base + row * 256 + ((col16 ^ (row & 7)) << 4);
}

// ---------------------------------------------------------------------------
// fused fp32 -> fp16 conversion (vectorized, 1 launch)
// ---------------------------------------------------------------------------
#define N_HS  (T * HID)
#define N_WQ  (QKV_N * HID)
#define N_WO  (HID * QD)

__global__ __launch_bounds__(256) void cvt_f16(const float* __restrict__ hs,
                                               const float* __restrict__ wq,
                                               const float* __restrict__ wo) {
    long idx = ((long)blockIdx.x * 256 + threadIdx.x) * 4;
    const float* src;
    __half* dst;
    long off;
    if (idx < N_HS)             { src = hs; dst = g_hsf; off = idx; }
    else if (idx < N_HS + N_WQ) { src = wq; dst = g_wqf; off = idx - N_HS; }
    else                        { src = wo; dst = g_wof; off = idx - N_HS - N_WQ; }
    float4 v = *(const float4*)(src + off);
    uint2 w = make_uint2(packh2(v.x, v.y), packh2(v.z, v.w));
    *(uint2*)(dst + off) = w;
}

// ---------------------------------------------------------------------------
// mma.sync fp16 NT GEMM, BK=64, single barrier per chunk, 3-stage, 2 CTAs/SM.
// B fragments via ldsm4 pairs (two n-tiles per instruction) -> half the
// B-side LDSM issue count vs ldsm2.
// ---------------------------------------------------------------------------
#define TILE_B   (128 * 144)
#define STAGE_B  (2 * TILE_B)
#define GSMEM    (3 * STAGE_B)

template<bool HALF_OUT>
__global__ __launch_bounds__(256, 2)
void gemm_hmma(const __half* __restrict__ A,
               const __half* __restrict__ B,
               void* __restrict__ Cv, int N) {
    extern __shared__ char smem[];
    const uint32_t sbase = smem_u32(smem);
    const int tid  = threadIdx.x;
    const int wid  = tid >> 5;
    const int lane = tid & 31;
    const int wm   = wid & 1;
    const int wn   = wid >> 1;
    const int bm   = blockIdx.y * 128;
    const int bn   = blockIdx.x * 128;

    const __half* srcs[2] = {A + (size_t)bm * GK, B + (size_t)bn * GK};

    auto load_chunk = [&](int stage, int k0) {
        uint32_t db = sbase + stage * STAGE_B;
#pragma unroll
        for (int t = 0; t < 2; t++) {
            const __half* s = srcs[t] + k0;
#pragma unroll
            for (int i = 0; i < 4; i++) {
                int seg = i * 256 + tid;
                int row = seg >> 3, c16 = seg & 7;
                cp16(db + t * TILE_B + row * 144 + c16 * 16,
                     s + (size_t)row * GK + c16 * 8);
            }
        }
        asm volatile("cp.async.commit_group;" ::: "memory");
    };

    float acc[4][4][4];
#pragma unroll
    for (int mt = 0; mt < 4; mt++)
#pragma unroll
        for (int nt = 0; nt < 4; nt++)
#pragma unroll
            for (int r = 0; r < 4; r++) acc[mt][nt][r] = 0.0f;

    load_chunk(0, 0);
    load_chunk(1, GCH);

    const int arow  = lane & 15;
    const int akoff = (lane >> 4) * 16;
    // B via ldsm4: m0,m1 = n-tile 2j (k-halves), m2,m3 = n-tile 2j+1
    const int brow4 = ((lane >> 4) << 3) + (lane & 7);
    const int bkoff = ((lane >> 3) & 1) * 16;

    for (int i = 0; i < NCH; i++) {
        if (i + 1 < NCH)
            asm volatile("cp.async.wait_group 1;" ::: "memory");
        else
            asm volatile("cp.async.wait_group 0;" ::: "memory");
        __syncthreads();
        if (i + 2 < NCH) load_chunk((i + 2) % 3, (i + 2) * GCH);

        uint32_t s0 = sbase + (i % 3) * STAGE_B;
        uint32_t aB = s0, bB = s0 + TILE_B;

#pragma unroll
        for (int kk = 0; kk < 4; kk++) {
            const int kb = kk * 32;
            uint32_t af[4][4], bf[2][4];
#pragma unroll
            for (int mt = 0; mt < 4; mt++)
                ldsm4(af[mt], aB + (uint32_t)((wm * 64 + mt * 16 + arow) * 144 + kb + akoff));
#pragma unroll
            for (int np2 = 0; np2 < 2; np2++)
                ldsm4(bf[np2], bB + (uint32_t)((wn * 32 + np2 * 16 + brow4) * 144 + kb + bkoff));
#pragma unroll
            for (int mt = 0; mt < 4; mt++)
#pragma unroll
                for (int nt = 0; nt < 4; nt++)
                    mma16816(acc[mt][nt], af[mt], &bf[nt >> 1][(nt & 1) * 2]);
        }
    }

#pragma unroll
    for (int mt = 0; mt < 4; mt++) {
        const int row0 = bm + wm * 64 + mt * 16 + (lane >> 2);
#pragma unroll
        for (int nt = 0; nt < 4; nt++) {
            const int col = bn + wn * 32 + nt * 8 + (lane & 3) * 2;
            if (HALF_OUT) {
                __half* C = (__half*)Cv;
                *(uint32_t*)&C[(size_t)row0 * N + col] =
                    packh2(acc[mt][nt][0], acc[mt][nt][1]);
                *(uint32_t*)&C[(size_t)(row0 + 8) * N + col] =
                    packh2(acc[mt][nt][2], acc[mt][nt][3]);
            } else {
                float* C = (float*)Cv;
                *(float2*)&C[(size_t)row0 * N + col] =
                    make_float2(acc[mt][nt][0], acc[mt][nt][1]);
                *(float2*)&C[(size_t)(row0 + 8) * N + col] =
                    make_float2(acc[mt][nt][2], acc[mt][nt][3]);
            }
        }
    }
}

// ---------------------------------------------------------------------------
// RoPE + RMSNorm, reads fp16 qkv. Emits fp16 q (pre-scaled), k.
// ---------------------------------------------------------------------------
__global__ __launch_bounds__(256) void rope_norm_kernel(
    const int* __restrict__ positions,
    const float* __restrict__ qnw,
    const float* __restrict__ knw) {
    const int t    = blockIdx.x;
    const int tid  = threadIdx.x;
    const int lane = tid & 31;
    const float pos  = (float)positions[t];
    const float qpre = 0.08838834764831845f * 1.4426950408889634f;

    __shared__ float cs[64], sn[64];
    __shared__ float red[8];

    if (tid < 64) {
        float inv = powf(10000.0f, -(float)(2 * tid) * (1.0f / 128.0f));
        sincosf(pos * inv, &sn[tid], &cs[tid]);
    }
    __syncthreads();

    const __half* base = g_qkvh + (size_t)t * QKV_N;

    const int head = tid >> 4;
    const int c4   = (tid & 15) * 4;
    float av[4], bv[4];
    {
        uint2 ar = *(const uint2*)(base + head * 128 + c4);
        uint2 br = *(const uint2*)(base + head * 128 + 64 + c4);
        __half2* ah = (__half2*)&ar;
        __half2* bh = (__half2*)&br;
        float2 a0 = __half22float2(ah[0]), a1 = __half22float2(ah[1]);
        float2 b0 = __half22float2(bh[0]), b1 = __half22float2(bh[1]);
        av[0] = a0.x; av[1] = a0.y; av[2] = a1.x; av[3] = a1.y;
        bv[0] = b0.x; bv[1] = b0.y; bv[2] = b1.x; bv[3] = b1.y;
    }
    float o1[4], o2[4];
    {
        float ss = 0.0f;
#pragma unroll
        for (int j = 0; j < 4; j++) {
            float cv = cs[c4 + j], sv = sn[c4 + j];
            o1[j] = av[j] * cv - bv[j] * sv;
            o2[j] = bv[j] * cv + av[j] * sv;
            ss += o1[j] * o1[j] + o2[j] * o2[j];
        }
#pragma unroll
        for (int off = 16; off; off >>= 1)
            ss += __shfl_xor_sync(0xffffffffu, ss, off);
        if (lane == 0) red[tid >> 5] = ss;
    }
    __syncthreads();
    {
        float tot = red[0] + red[1] + red[2] + red[3] +
                    red[4] + red[5] + red[6] + red[7];
        float qs = rsqrtf(tot * (1.0f / QD) + EPSV) * qpre;
        float4 w1 = *(const float4*)(qnw + head * 128 + c4);
        float4 w2 = *(const float4*)(qnw + head * 128 + 64 + c4);
        __half* dst = g_qf + (size_t)t * QD + head * 128 + c4;
        *(uint2*)dst = make_uint2(packh2(o1[0] * qs * w1.x, o1[1] * qs * w1.y),
                                  packh2(o1[2] * qs * w1.z, o1[3] * qs * w1.w));
        *(uint2*)(dst + 64) = make_uint2(packh2(o2[0] * qs * w2.x, o2[1] * qs * w2.y),
                                         packh2(o2[2] * qs * w2.z, o2[3] * qs * w2.w));
    }
    __syncthreads();

    const int khead = tid >> 6;
    const int fi    = tid & 63;
    const __half* kp = base + QD + khead * 128 + fi;
    float k1, k2;
    {
        float ka = __half2float(kp[0]), kb = __half2float(kp[64]);
        float cv = cs[fi], sv = sn[fi];
        k1 = ka * cv - kb * sv;
        k2 = kb * cv + ka * sv;
        float ss = k1 * k1 + k2 * k2;
#pragma unroll
        for (int off = 16; off; off >>= 1)
            ss += __shfl_xor_sync(0xffffffffu, ss, off);
        if (lane == 0) red[tid >> 5] = ss;
    }
    __syncthreads();
    {
        float tot = red[0] + red[1] + red[2] + red[3] +
                    red[4] + red[5] + red[6] + red[7];
        float ks = rsqrtf(tot * (1.0f / KD) + EPSV);
        __half* dst = g_kf + (size_t)t * KD + khead * 128 + fi;
        dst[0]  = __float2half_rn(k1 * ks * knw[khead * 128 + fi]);
        dst[64] = __float2half_rn(k2 * ks * knw[khead * 128 + 64 + fi]);
    }
    // V: consumed directly from g_qkvh by flash (no copy)
}

// ---------------------------------------------------------------------------
// flash_mma: byte-identical to the round-12 best (254.3us): exp2f softmax
// phase with p2 staging, 128-key tiles, 2 CTAs/SM, K double-buffered,
// V single-buffered; K(it+2) commit after the first barrier, V(it+1) after
// the post-PV barrier.
// ---------------------------------------------------------------------------
#define QSZ     16384                      // 64 rows x 256 B
#define KSZ     32768                      // 128 rows x 256 B
#define VSZ     32768
#define FSMEM   (QSZ + 2 * KSZ + VSZ)      // 114688 -> 2 CTAs/SM

__global__ __launch_bounds__(128, 2) void flash_mma() {
    extern __shared__ char smem[];
    const uint32_t sbase = smem_u32(smem);
    const int tid  = threadIdx.x;
    const int wg   = tid >> 5;
    const int lane = tid & 31;
    const int h    = blockIdx.y;
    const int kvh  = h >> 2;
    const int qb   = (int)gridDim.x - 1 - (int)blockIdx.x;
    const int q0   = qb * 64;
    const int nt   = qb / 2 + 1;           // 128-key tiles covering [0, q0+64)

    const uint32_t qB = sbase;
    const uint32_t vB = sbase + QSZ + 2 * KSZ;

    auto load_k = [&](int stage, int k0) {
        const __half* ks = g_kf + (size_t)k0 * KD + kvh * D;
        uint32_t kb = sbase + QSZ + stage * KSZ;
#pragma unroll
        for (int i = 0; i < 16; i++) {
            int seg = i * 128 + tid;
            int row = seg >> 4, c = seg & 15;
            cp16(swz(kb, row, c), ks + (size_t)row * KD + c * 8);
        }
    };
    auto load_v = [&](int k0) {
        const __half* vs = g_qkvh + (size_t)k0 * QKV_N + QD + KD + kvh * D;
#pragma unroll
        for (int i = 0; i < 16; i++) {
            int seg = i * 128 + tid;
            int row = seg >> 4, c = seg & 15;
            cp16(swz(vB, row, c), vs + (size_t)row * QKV_N + c * 8);
        }
    };

    // ---- prologue: {Q, K0, V0} then {K1} ----
    {
        const __half* qs = g_qf + (size_t)q0 * QD + h * D;
#pragma unroll
        for (int i = 0; i < 8; i++) {
            int seg = i * 128 + tid;
            int row = seg >> 4, c = seg & 15;
            cp16(swz(qB, row, c), qs + (size_t)row * QD + c * 8);
        }
        load_k(0, 0);
        load_v(0);
        asm volatile("cp.async.commit_group;" ::: "memory");
    }
    if (nt > 1) {
        load_k(1, 128);
        asm volatile("cp.async.commit_group;" ::: "memory");
        asm volatile("cp.async.wait_group 1;" ::: "memory");
    } else {
        asm volatile("cp.async.wait_group 0;" ::: "memory");
    }
    __syncthreads();

    // per-lane fragment coordinates
    const int qrow = wg * 16 + (lane & 15);
    const int qhi  = lane >> 4;
    const int krow = ((lane >> 4) << 3) + (lane & 7);
    const int khi  = (lane >> 3) & 1;
    const int vrow = (((lane >> 3) & 1) << 3) + (lane & 7);
    const int vhi  = lane >> 4;
    const int r_lo = q0 + wg * 16 + (lane >> 2);
    const int r_hi = r_lo + 8;

    float o[16][4];
#pragma unroll
    for (int ntl = 0; ntl < 16; ntl++)
#pragma unroll
        for (int r = 0; r < 4; r++) o[ntl][r] = 0.0f;
    float m_lo = -1e30f, m_hi = -1e30f, l_lo = 0.0f, l_hi = 0.0f;

    float s[16][4];

    auto compute_S = [&](int stage) {
        const uint32_t kb = sbase + QSZ + stage * KSZ;
#pragma unroll
        for (int ntl = 0; ntl < 16; ntl++)
#pragma unroll
            for (int r = 0; r < 4; r++) s[ntl][r] = 0.0f;
#pragma unroll
        for (int kk = 0; kk < 8; kk++) {
            uint32_t af[4];
            ldsm4(af, swz(qB, qrow, kk * 2 + qhi));
#pragma unroll
            for (int np = 0; np < 8; np++) {
                uint32_t bf[4];
                ldsm4(bf, swz(kb, np * 16 + krow, kk * 2 + khi));
                mma16816(s[2 * np],     af, &bf[0]);
                mma16816(s[2 * np + 1], af, &bf[2]);
            }
        }
    };

    compute_S(0);

    for (int it = 0; it < nt; it++) {
        // ---- softmax(it) ----
        if (it == nt - 1) {
#pragma unroll
            for (int ntl = 0; ntl < 16; ntl++) {
#pragma unroll
                for (int c = 0; c < 2; c++) {
                    int key = it * 128 + ntl * 8 + (lane & 3) * 2 + c;
                    if (key > r_lo) s[ntl][c]     = -1e30f;
                    if (key > r_hi) s[ntl][2 + c] = -1e30f;
                }
            }
        }
        float mx_lo = -1e30f, mx_hi = -1e30f;
#pragma unroll
        for (int ntl = 0; ntl < 16; ntl++) {
            mx_lo = fmaxf(mx_lo, fmaxf(s[ntl][0], s[ntl][1]));
            mx_hi = fmaxf(mx_hi, fmaxf(s[ntl][2], s[ntl][3]));
        }
        mx_lo = fmaxf(mx_lo, __shfl_xor_sync(0xffffffffu, mx_lo, 1));
        mx_lo = fmaxf(mx_lo, __shfl_xor_sync(0xffffffffu, mx_lo, 2));
        mx_hi = fmaxf(mx_hi, __shfl_xor_sync(0xffffffffu, mx_hi, 1));
        mx_hi = fmaxf(mx_hi, __shfl_xor_sync(0xffffffffu, mx_hi, 2));
        float mn_lo = fmaxf(m_lo, mx_lo);
        float mn_hi = fmaxf(m_hi, mx_hi);
        float cr_lo = exp2f(m_lo - mn_lo);
        float cr_hi = exp2f(m_hi - mn_hi);
        m_lo = mn_lo; m_hi = mn_hi;

        uint32_t p2[16][2];
        float sum_lo = 0.0f, sum_hi = 0.0f;
#pragma unroll
        for (int ntl = 0; ntl < 16; ntl++) {
            float p0 = exp2f(s[ntl][0] - m_lo);
            float p1 = exp2f(s[ntl][1] - m_lo);
            float pc = exp2f(s[ntl][2] - m_hi);
            float p3 = exp2f(s[ntl][3] - m_hi);
            sum_lo += p0 + p1;
            sum_hi += pc + p3;
            p2[ntl][0] = packh2(p0, p1);
            p2[ntl][1] = packh2(pc, p3);
        }
        bool need = (cr_lo != 1.0f) || (cr_hi != 1.0f);
        if (__any_sync(0xffffffffu, need)) {
            l_lo = l_lo * cr_lo + sum_lo;
            l_hi = l_hi * cr_hi + sum_hi;
#pragma unroll
            for (int ntl = 0; ntl < 16; ntl++) {
                o[ntl][0] *= cr_lo; o[ntl][1] *= cr_lo;
                o[ntl][2] *= cr_hi; o[ntl][3] *= cr_hi;
            }
        } else {
            l_lo += sum_lo;
            l_hi += sum_hi;
        }

        // ---- V(it) resident ----
        asm volatile("cp.async.wait_group 0;" ::: "memory");
        __syncthreads();

        // ---- K(it+2) commit: stage it&1 free ----
        if (it + 2 < nt) {
            load_k(it & 1, (it + 2) * 128);
            asm volatile("cp.async.commit_group;" ::: "memory");
        }

        // ---- PV(it) ----
#pragma unroll
        for (int kk = 0; kk < 8; kk++) {
            uint32_t pa[4] = {p2[2 * kk][0], p2[2 * kk][1],
                              p2[2 * kk + 1][0], p2[2 * kk + 1][1]};
#pragma unroll
            for (int nd = 0; nd < 8; nd++) {
                uint32_t vf[4];
                ldsm4t(vf, swz(vB, kk * 16 + vrow, nd * 2 + vhi));
                mma16816(o[2 * nd],     pa, &vf[0]);
                mma16816(o[2 * nd + 1], pa, &vf[2]);
            }
        }
        __syncthreads();                      // V buffer free

        // ---- V(it+1) commit, then S(it+1) ----
        if (it + 1 < nt) {
            load_v((it + 1) * 128);
            asm volatile("cp.async.commit_group;" ::: "memory");
            compute_S((it + 1) & 1);
        }
    }

    // ---- epilogue ----
    l_lo += __shfl_xor_sync(0xffffffffu, l_lo, 1);
    l_lo += __shfl_xor_sync(0xffffffffu, l_lo, 2);
    l_hi += __shfl_xor_sync(0xffffffffu, l_hi, 1);
    l_hi += __shfl_xor_sync(0xffffffffu, l_hi, 2);
    const float inv_lo = 1.0f / l_lo;
    const float inv_hi = 1.0f / l_hi;
#pragma unroll
    for (int ntl = 0; ntl < 16; ntl++) {
        int col = h * D + ntl * 8 + (lane & 3) * 2;
        *(uint32_t*)&g_atf[(size_t)r_lo * QD + col] =
            packh2(o[ntl][0] * inv_lo, o[ntl][1] * inv_lo);
        *(uint32_t*)&g_atf[(size_t)r_hi * QD + col] =
            packh2(o[ntl][2] * inv_hi, o[ntl][3] * inv_hi);
    }
}

// ---------------------------------------------------------------------------
// Launch
// ---------------------------------------------------------------------------
extern "C" void kernel_launch(void* const* d_in, const int* in_sizes, int n_in,
                              void* d_out, int out_size) {
    const int*   positions = (const int*)d_in[0];
    const float* hs        = (const float*)d_in[1];
    const float* w_qkv     = (const float*)d_in[2];
    const float* w_o       = (const float*)d_in[3];
    const float* qnw       = (const float*)d_in[4];
    const float* knw       = (const float*)d_in[5];
    float*       out       = (float*)d_out;

    __half *qkvh, *hsf, *wqf, *wof, *atf;
    cudaGetSymbolAddress((void**)&qkvh, g_qkvh);
    cudaGetSymbolAddress((void**)&hsf, g_hsf);
    cudaGetSymbolAddress((void**)&wqf, g_wqf);
    cudaGetSymbolAddress((void**)&wof, g_wof);
    cudaGetSymbolAddress((void**)&atf, g_atf);

    static bool attr_set = false;
    if (!attr_set) {
        cudaFuncSetAttribute(gemm_hmma<true>,
                             cudaFuncAttributeMaxDynamicSharedMemorySize, GSMEM);
        cudaFuncSetAttribute(gemm_hmma<false>,
                             cudaFuncAttributeMaxDynamicSharedMemorySize, GSMEM);
        cudaFuncSetAttribute(flash_mma,
                             cudaFuncAttributeMaxDynamicSharedMemorySize, FSMEM);
        attr_set = true;
    }

    // 1) fused fp32->fp16 conversions
    cvt_f16<<<(N_HS + N_WQ + N_WO) / 1024, 256>>>(hs, w_qkv, w_o);
    // 2) QKV projection (fp16 output)
    {
        dim3 grid(QKV_N / 128, T / 128);
        gemm_hmma<true><<<grid, 256, GSMEM>>>(hsf, wqf, qkvh, QKV_N);
    }
    // 3) RoPE + RMSNorm (reads fp16 qkv)
    rope_norm_kernel<<<T, 256>>>(positions, qnw, knw);
    // 4) Causal GQA attention (round-12 configuration)
    {
        dim3 grid(T / 64, H);
        flash_mma<<<grid, 128, FSMEM>>>();
    }
    // 5) Output projection (fp32 output)
    {
        dim3 grid(HID / 128, T / 128);
        gemm_hmma<false><<<grid, 256, GSMEM>>>(atf, wof, out, HID);
    }
}